// round 15
// baseline (speedup 1.0000x reference)
#include <cuda_runtime.h>
#include <cuda_bf16.h>
#include <math.h>

#define N_NODES 50000
#define N_EDGES 800000
#define DIM     128
#define HEADS   8
#define GRAPHS  64
#define NCLASS  10
#define SLOPE   0.2f
#define BN_EPS  1e-5f
#define NB_CSR  148
#define LOG2E   1.4426950408889634f
#define MAX_PADDED (N_EDGES + 4 * N_NODES)

// ---------------- scratch (device globals) ----------------------------------
__device__ __nv_bfloat16 g_h[(N_NODES + 1) * DIM];  // +1: sentinel row (zero-init)
__device__ __nv_bfloat16 g_midb[N_NODES * DIM];     // layer1 output, bf16
__device__ float g_w1p[DIM * DIM];
__device__ float g_w2p[DIM * DIM];
__device__ float g_asrc[(N_NODES + 1) * 16];        // stride-16, log2e-scaled
__device__ float g_adst[N_NODES * HEADS];           // log2e-scaled
__device__ int   g_deg[N_NODES];
__device__ int   g_off[N_NODES + 1];
__device__ int   g_cur[N_NODES];
__device__ int   g_srcs[MAX_PADDED];                // stores src*16 (uint4 H index)
__device__ int   g_sentq[4];                        // sentinel quad {N_NODES*16 x4}
__device__ float g_gsum[GRAPHS * DIM];
__device__ float g_gcnt[GRAPHS];
__device__ int   g_barcnt = 0;
__device__ int   g_bargen = 0;
__device__ int   g_bsum[NB_CSR];

__device__ __forceinline__ float leaky(float x) { return fmaxf(x, SLOPE * x); }

__device__ __forceinline__ float ex2(float x)
{
    float r;
    asm("ex2.approx.f32 %0, %1;" : "=f"(r) : "f"(x));
    return r;
}

__device__ __forceinline__ void bf16x8_unpack(uint4 v, float2& f0, float2& f1,
                                              float2& f2, float2& f3)
{
    f0 = __bfloat1622float2(*(const __nv_bfloat162*)&v.x);
    f1 = __bfloat1622float2(*(const __nv_bfloat162*)&v.y);
    f2 = __bfloat1622float2(*(const __nv_bfloat162*)&v.z);
    f3 = __bfloat1622float2(*(const __nv_bfloat162*)&v.w);
}

__device__ __forceinline__ unsigned int f2tf32(float f)
{
    unsigned int u;
    asm("cvt.rna.tf32.f32 %0, %1;" : "=r"(u) : "f"(f));
    return u;
}

// sense-reversing grid barrier (all NB_CSR blocks resident)
__device__ __forceinline__ void grid_barrier()
{
    __syncthreads();
    if (threadIdx.x == 0) {
        __threadfence();
        int gen = ((volatile int*)&g_bargen)[0];
        if (atomicAdd(&g_barcnt, 1) == (int)gridDim.x - 1) {
            g_barcnt = 0;
            __threadfence();
            atomicAdd(&g_bargen, 1);
        } else {
            while (((volatile int*)&g_bargen)[0] == gen) { }
        }
        __threadfence();
    }
    __syncthreads();
}

// ---------------- fused CSR build (padded to 4, src*16) + pool counts --------
__global__ void __launch_bounds__(256) build_csr(
        const int* __restrict__ esrc, const int* __restrict__ edst,
        const int* __restrict__ batch,
        int* __restrict__ deg, int* __restrict__ off, int* __restrict__ cur,
        int* __restrict__ srcs, float* __restrict__ gsum, float* __restrict__ gcnt)
{
    __shared__ int sm[256];
    __shared__ int bh[GRAPHS];
    int t   = threadIdx.x;
    int gid = blockIdx.x * 256 + t;
    const int stride = NB_CSR * 256;

    for (int i = gid; i < N_NODES; i += stride) deg[i] = 0;
    for (int i = gid; i < GRAPHS * DIM; i += stride) gsum[i] = 0.f;
    if (gid < GRAPHS) gcnt[gid] = 0.f;
    if (gid < 4) g_sentq[gid] = N_NODES * 16;
    if (t < GRAPHS) bh[t] = 0;
    grid_barrier();                                    // B1

    for (int e = gid; e < N_EDGES; e += stride) atomicAdd(&deg[edst[e]], 1);
    for (int i = gid; i < N_NODES; i += stride) atomicAdd(&bh[batch[i]], 1);
    __syncthreads();
    if (t < GRAPHS && bh[t] > 0) atomicAdd(&gcnt[t], (float)bh[t]);
    grid_barrier();                                    // B2

    int i0 = gid * 2, i1 = gid * 2 + 1;
    int d0 = (i0 < N_NODES) ? deg[i0] : 0;
    int d1 = (i1 < N_NODES) ? deg[i1] : 0;
    int p0 = (d0 + 3) & ~3;
    int p1 = (d1 + 3) & ~3;
    int msum = p0 + p1;
    sm[t] = msum;
    __syncthreads();
    for (int d = 1; d < 256; d <<= 1) {
        int u = (t >= d) ? sm[t - d] : 0;
        __syncthreads();
        sm[t] += u;
        __syncthreads();
    }
    if (t == 255) g_bsum[blockIdx.x] = sm[255];
    int texcl = sm[t] - msum;
    grid_barrier();                                    // B3
    if (blockIdx.x == 0 && t == 0) {
        int run = 0;
        for (int i = 0; i < NB_CSR; i++) { int v = g_bsum[i]; g_bsum[i] = run; run += v; }
        off[N_NODES] = run;
    }
    grid_barrier();                                    // B4
    int base = g_bsum[blockIdx.x] + texcl;
    if (i0 < N_NODES) { off[i0] = base;      cur[i0] = base; }
    if (i1 < N_NODES) { off[i1] = base + p0; cur[i1] = base + p0; }
    grid_barrier();                                    // B5

    for (int e = gid; e < N_EDGES; e += stride) {
        int pos = atomicAdd(&cur[edst[e]], 1);
        srcs[pos] = esrc[e] * 16;                     // pre-scaled uint4/aS16 index
    }
    for (int i = gid; i < N_NODES; i += stride) {
        int st = off[i] + deg[i], en = off[i + 1];
        for (int j = st; j < en; j++) srcs[j] = N_NODES * 16;
    }
}

// ---------------- W pack: tf32 + mma-fragment-major ---------------------------
__global__ void pack_w_tf32(const float* __restrict__ W1, const float* __restrict__ W2,
                            float* __restrict__ P1, float* __restrict__ P2)
{
    int i = blockIdx.x * blockDim.x + threadIdx.x;
    if (i >= 16 * 8 * 32) return;
    int lane = i & 31;
    int p    = (i >> 5) & 7;
    int ks   = i >> 8;
    int kc = lane & 3, nc = lane >> 2;
    int r0 = ks * 8 + kc, r1 = r0 + 4;
    int c0 = (2 * p) * 8 + nc, c1 = (2 * p + 1) * 8 + nc;
    float4 v1, v2;
    v1.x = __uint_as_float(f2tf32(W1[r0 * DIM + c0]));
    v1.y = __uint_as_float(f2tf32(W1[r1 * DIM + c0]));
    v1.z = __uint_as_float(f2tf32(W1[r0 * DIM + c1]));
    v1.w = __uint_as_float(f2tf32(W1[r1 * DIM + c1]));
    v2.x = __uint_as_float(f2tf32(W2[r0 * DIM + c0]));
    v2.y = __uint_as_float(f2tf32(W2[r1 * DIM + c0]));
    v2.z = __uint_as_float(f2tf32(W2[r0 * DIM + c1]));
    v2.w = __uint_as_float(f2tf32(W2[r1 * DIM + c1]));
    ((float4*)P1)[i] = v1;
    ((float4*)P2)[i] = v2;
}

// ---------------- tensor-core GEMM (h = X @ W, tf32 mma) ---------------------
// scores stored log2e-scaled; aS padded to stride 16.
__global__ void __launch_bounds__(256, 2) gemm_mma_kernel(
        const float* __restrict__ X,
        const float* __restrict__ Wpack,
        const float* __restrict__ attS,
        const float* __restrict__ attD,
        __nv_bfloat16* __restrict__ Hout,
        float* __restrict__ aS,
        float* __restrict__ aD,
        int heads, int in_bf16)
{
    extern __shared__ float xsm[];            // 128 * 132 floats
    __shared__ float sS[DIM], sD[DIM];
    int tid  = threadIdx.x;
    int lane = tid & 31;
    int w    = tid >> 5;
    if (tid < DIM) { sS[tid] = attS[tid]; sD[tid] = attD[tid]; }

    // sentinel scores: padding edges contribute ex2(-1e4) = 0
    if (blockIdx.x == 0 && tid < heads) aS[N_NODES * 16 + tid] = -1e4f;

    int row0 = blockIdx.x * 128;
    if (!in_bf16) {
        const float4* X4 = (const float4*)X;
#pragma unroll
        for (int j = 0; j < 16; j++) {
            int idx = tid + j * 256;
            int r = idx >> 5, c = idx & 31;
            float4 v = (row0 + r < N_NODES) ? X4[(row0 + r) * 32 + c]
                                            : make_float4(0.f, 0.f, 0.f, 0.f);
            *(float4*)&xsm[r * 132 + c * 4] = v;
        }
    } else {
        const uint4* Xb = (const uint4*)X;
#pragma unroll
        for (int j = 0; j < 8; j++) {
            int idx = tid + j * 256;              // 0..2047
            int r = idx >> 4, c = idx & 15;
            uint4 v = (row0 + r < N_NODES) ? Xb[(row0 + r) * 16 + c]
                                           : make_uint4(0, 0, 0, 0);
            float2 f0, f1, f2, f3;
            bf16x8_unpack(v, f0, f1, f2, f3);
            *(float4*)&xsm[r * 132 + c * 8]     = make_float4(f0.x, f0.y, f1.x, f1.y);
            *(float4*)&xsm[r * 132 + c * 8 + 4] = make_float4(f2.x, f2.y, f3.x, f3.y);
        }
    }
    __syncthreads();

    int m0w = w * 16;
    if (row0 + m0w >= N_NODES) return;

    int kc = lane & 3;
    int nc = lane >> 2;
    const float* x1 = xsm + (m0w + nc) * 132;
    const float* x2 = x1 + 8 * 132;

    float acc[16][4];
#pragma unroll
    for (int nt = 0; nt < 16; nt++) {
        acc[nt][0] = 0.f; acc[nt][1] = 0.f; acc[nt][2] = 0.f; acc[nt][3] = 0.f;
    }

    const float4* Wp4 = (const float4*)Wpack;
#pragma unroll
    for (int ks = 0; ks < 16; ks++) {
        int k0 = ks * 8;
        unsigned int a0 = f2tf32(x1[k0 + kc]);
        unsigned int a1 = f2tf32(x2[k0 + kc]);
        unsigned int a2 = f2tf32(x1[k0 + kc + 4]);
        unsigned int a3 = f2tf32(x2[k0 + kc + 4]);
#pragma unroll
        for (int p = 0; p < 8; p++) {
            float4 bb = Wp4[(ks * 8 + p) * 32 + lane];
            asm("mma.sync.aligned.m16n8k8.row.col.f32.tf32.tf32.f32 "
                "{%0,%1,%2,%3}, {%4,%5,%6,%7}, {%8,%9}, {%0,%1,%2,%3};"
                : "+f"(acc[2*p][0]), "+f"(acc[2*p][1]), "+f"(acc[2*p][2]), "+f"(acc[2*p][3])
                : "r"(a0), "r"(a1), "r"(a2), "r"(a3),
                  "r"(__float_as_uint(bb.x)), "r"(__float_as_uint(bb.y)));
            asm("mma.sync.aligned.m16n8k8.row.col.f32.tf32.tf32.f32 "
                "{%0,%1,%2,%3}, {%4,%5,%6,%7}, {%8,%9}, {%0,%1,%2,%3};"
                : "+f"(acc[2*p+1][0]), "+f"(acc[2*p+1][1]), "+f"(acc[2*p+1][2]), "+f"(acc[2*p+1][3])
                : "r"(a0), "r"(a1), "r"(a2), "r"(a3),
                  "r"(__float_as_uint(bb.z)), "r"(__float_as_uint(bb.w)));
        }
    }

    int cb2 = (lane & 3) * 2;
    int r1 = row0 + m0w + nc;
    int r2 = r1 + 8;

#pragma unroll
    for (int rr = 0; rr < 2; rr++) {
        int row = (rr == 0) ? r1 : r2;
#pragma unroll
        for (int nt = 0; nt < 16; nt++) {
            __nv_bfloat162 pr = __floats2bfloat162_rn(acc[nt][rr * 2], acc[nt][rr * 2 + 1]);
            *(__nv_bfloat162*)(Hout + row * DIM + nt * 8 + cb2) = pr;
        }
        float tps = 0.f, tpd = 0.f;
#pragma unroll
        for (int h = 0; h < 8; h++) {
            int c0 = h * 16 + cb2;
            float v0 = acc[2 * h][rr * 2],     v1 = acc[2 * h][rr * 2 + 1];
            float v2 = acc[2 * h + 1][rr * 2], v3 = acc[2 * h + 1][rr * 2 + 1];
            float ps = v0 * sS[c0] + v1 * sS[c0 + 1] + v2 * sS[c0 + 8] + v3 * sS[c0 + 9];
            float pd = v0 * sD[c0] + v1 * sD[c0 + 1] + v2 * sD[c0 + 8] + v3 * sD[c0 + 9];
            ps += __shfl_xor_sync(0xffffffff, ps, 1);
            ps += __shfl_xor_sync(0xffffffff, ps, 2);
            pd += __shfl_xor_sync(0xffffffff, pd, 1);
            pd += __shfl_xor_sync(0xffffffff, pd, 2);
            if (heads == HEADS) {
                if ((lane & 3) == 0) {
                    aS[row * 16 + h]       = ps * LOG2E;
                    aD[row * HEADS + h]    = pd * LOG2E;
                }
            } else { tps += ps; tpd += pd; }
        }
        if (heads == 1 && (lane & 3) == 0) {
            aS[row * 16] = tps * LOG2E;
            aD[row]      = tpd * LOG2E;
        }
    }
}

// ---------------- agg edge-quad bodies ----------------------------------------
#define AGG1_QUAD(s4)                                                          \
    do {                                                                       \
        float s0 = aS[(s4).x + h];                                             \
        float s1 = aS[(s4).y + h];                                             \
        float s2 = aS[(s4).z + h];                                             \
        float s3 = aS[(s4).w + h];                                             \
        uint4 h0 = H4[(s4).x + q];                                             \
        uint4 h1 = H4[(s4).y + q];                                             \
        uint4 h2 = H4[(s4).z + q];                                             \
        uint4 h3 = H4[(s4).w + q];                                             \
        float e0 = ex2(leaky(s0 + aD_h));                                      \
        float e1 = ex2(leaky(s1 + aD_h));                                      \
        float e2 = ex2(leaky(s2 + aD_h));                                      \
        float e3 = ex2(leaky(s3 + aD_h));                                      \
        den += (e0 + e1) + (e2 + e3);                                          \
        float2 f0, f1, f2, f3;                                                 \
        bf16x8_unpack(h0, f0, f1, f2, f3);                                     \
        a0 = fmaf(f0.x, e0, a0); a1 = fmaf(f0.y, e0, a1);                      \
        a2 = fmaf(f1.x, e0, a2); a3 = fmaf(f1.y, e0, a3);                      \
        a4 = fmaf(f2.x, e0, a4); a5 = fmaf(f2.y, e0, a5);                      \
        a6 = fmaf(f3.x, e0, a6); a7 = fmaf(f3.y, e0, a7);                      \
        bf16x8_unpack(h1, f0, f1, f2, f3);                                     \
        a0 = fmaf(f0.x, e1, a0); a1 = fmaf(f0.y, e1, a1);                      \
        a2 = fmaf(f1.x, e1, a2); a3 = fmaf(f1.y, e1, a3);                      \
        a4 = fmaf(f2.x, e1, a4); a5 = fmaf(f2.y, e1, a5);                      \
        a6 = fmaf(f3.x, e1, a6); a7 = fmaf(f3.y, e1, a7);                      \
        bf16x8_unpack(h2, f0, f1, f2, f3);                                     \
        a0 = fmaf(f0.x, e2, a0); a1 = fmaf(f0.y, e2, a1);                      \
        a2 = fmaf(f1.x, e2, a2); a3 = fmaf(f1.y, e2, a3);                      \
        a4 = fmaf(f2.x, e2, a4); a5 = fmaf(f2.y, e2, a5);                      \
        a6 = fmaf(f3.x, e2, a6); a7 = fmaf(f3.y, e2, a7);                      \
        bf16x8_unpack(h3, f0, f1, f2, f3);                                     \
        a0 = fmaf(f0.x, e3, a0); a1 = fmaf(f0.y, e3, a1);                      \
        a2 = fmaf(f1.x, e3, a2); a3 = fmaf(f1.y, e3, a3);                      \
        a4 = fmaf(f2.x, e3, a4); a5 = fmaf(f2.y, e3, a5);                      \
        a6 = fmaf(f3.x, e3, a6); a7 = fmaf(f3.y, e3, a7);                      \
    } while (0)

#define AGG2_QUAD(s4)                                                          \
    do {                                                                       \
        float s0 = aS[(s4).x];                                                 \
        float s1 = aS[(s4).y];                                                 \
        float s2 = aS[(s4).z];                                                 \
        float s3 = aS[(s4).w];                                                 \
        uint4 h0 = H4[(s4).x + q];                                             \
        uint4 h1 = H4[(s4).y + q];                                             \
        uint4 h2 = H4[(s4).z + q];                                             \
        uint4 h3 = H4[(s4).w + q];                                             \
        float e0 = ex2(leaky(s0 + aDn));                                       \
        float e1 = ex2(leaky(s1 + aDn));                                       \
        float e2 = ex2(leaky(s2 + aDn));                                       \
        float e3 = ex2(leaky(s3 + aDn));                                       \
        den += (e0 + e1) + (e2 + e3);                                          \
        float2 f0, f1, f2, f3;                                                 \
        bf16x8_unpack(h0, f0, f1, f2, f3);                                     \
        a0 = fmaf(f0.x, e0, a0); a1 = fmaf(f0.y, e0, a1);                      \
        a2 = fmaf(f1.x, e0, a2); a3 = fmaf(f1.y, e0, a3);                      \
        a4 = fmaf(f2.x, e0, a4); a5 = fmaf(f2.y, e0, a5);                      \
        a6 = fmaf(f3.x, e0, a6); a7 = fmaf(f3.y, e0, a7);                      \
        bf16x8_unpack(h1, f0, f1, f2, f3);                                     \
        a0 = fmaf(f0.x, e1, a0); a1 = fmaf(f0.y, e1, a1);                      \
        a2 = fmaf(f1.x, e1, a2); a3 = fmaf(f1.y, e1, a3);                      \
        a4 = fmaf(f2.x, e1, a4); a5 = fmaf(f2.y, e1, a5);                      \
        a6 = fmaf(f3.x, e1, a6); a7 = fmaf(f3.y, e1, a7);                      \
        bf16x8_unpack(h2, f0, f1, f2, f3);                                     \
        a0 = fmaf(f0.x, e2, a0); a1 = fmaf(f0.y, e2, a1);                      \
        a2 = fmaf(f1.x, e2, a2); a3 = fmaf(f1.y, e2, a3);                      \
        a4 = fmaf(f2.x, e2, a4); a5 = fmaf(f2.y, e2, a5);                      \
        a6 = fmaf(f3.x, e2, a6); a7 = fmaf(f3.y, e2, a7);                      \
        bf16x8_unpack(h3, f0, f1, f2, f3);                                     \
        a0 = fmaf(f0.x, e3, a0); a1 = fmaf(f0.y, e3, a1);                      \
        a2 = fmaf(f1.x, e3, a2); a3 = fmaf(f1.y, e3, a3);                      \
        a4 = fmaf(f2.x, e3, a4); a5 = fmaf(f2.y, e3, a5);                      \
        a6 = fmaf(f3.x, e3, a6); a7 = fmaf(f3.y, e3, a7);                      \
    } while (0)

// ---------------- layer 1 fused aggregation (+bias+BN+ELU, bf16 out) --------
__global__ void __launch_bounds__(256, 6) agg_layer1(
        const int* __restrict__ srcs, const int* __restrict__ off,
        const float* __restrict__ aS, const float* __restrict__ aD,
        const __nv_bfloat16* __restrict__ H,
        const float* __restrict__ b1,
        const float* __restrict__ bn_g, const float* __restrict__ bn_b,
        const float* __restrict__ bn_m, const float* __restrict__ bn_v,
        __nv_bfloat16* __restrict__ out)
{
    int wid  = threadIdx.x >> 5;
    int lane = threadIdx.x & 31;
    int q    = lane & 15;
    int half = lane >> 4;
    int node = blockIdx.x * 16 + wid * 2 + half;   // 50000 = 3125*16, always valid
    int h    = q >> 1;
    const uint4* H4 = (const uint4*)H;

    float aD_h = aD[node * HEADS + h];
    float den  = ex2(leaky(aS[node * 16 + h] + aD_h));   // self loop
    float2 u0, u1, u2, u3;
    bf16x8_unpack(H4[node * 16 + q], u0, u1, u2, u3);
    float a0 = u0.x * den, a1 = u0.y * den, a2 = u1.x * den, a3 = u1.y * den;
    float a4 = u2.x * den, a5 = u2.y * den, a6 = u3.x * den, a7 = u3.y * den;

    int beg = off[node];
    int n   = off[node + 1] - beg;        // multiple of 4
    int noth = __shfl_xor_sync(0xffffffff, n, 16);
    int nqmin = min(n, noth) >> 2;
    int nqmax = max(n, noth) >> 2;
    int nq    = n >> 2;
    const int4* base = (const int4*)(srcs + beg);

    int iq = 0;
#pragma unroll 2
    for (; iq < nqmin; iq++) {
        int4 s4 = base[iq];
        AGG1_QUAD(s4);
    }
    for (; iq < nqmax; iq++) {
        int4 s4 = (iq < nq) ? base[iq] : *(const int4*)g_sentq;
        AGG1_QUAD(s4);
    }
    float inv = 1.f / den;

    // epilogue: + b1, BN(eval), ELU, bf16 pack
    const float4* B1 = (const float4*)b1;
    const float4* GG = (const float4*)bn_g;
    const float4* BE = (const float4*)bn_b;
    const float4* MU = (const float4*)bn_m;
    const float4* VA = (const float4*)bn_v;
    float r[8] = {a0, a1, a2, a3, a4, a5, a6, a7};
    float4 oo[2];
#pragma unroll
    for (int p = 0; p < 2; p++) {
        float4 bb = B1[q * 2 + p];
        float4 gg = GG[q * 2 + p];
        float4 be = BE[q * 2 + p];
        float4 mu = MU[q * 2 + p];
        float4 va = VA[q * 2 + p];
        float4 o;
        o.x = (r[p*4+0] * inv + bb.x - mu.x) * gg.x * rsqrtf(va.x + BN_EPS) + be.x;
        o.y = (r[p*4+1] * inv + bb.y - mu.y) * gg.y * rsqrtf(va.y + BN_EPS) + be.y;
        o.z = (r[p*4+2] * inv + bb.z - mu.z) * gg.z * rsqrtf(va.z + BN_EPS) + be.z;
        o.w = (r[p*4+3] * inv + bb.w - mu.w) * gg.w * rsqrtf(va.w + BN_EPS) + be.w;
        o.x = o.x > 0.f ? o.x : expm1f(o.x);
        o.y = o.y > 0.f ? o.y : expm1f(o.y);
        o.z = o.z > 0.f ? o.z : expm1f(o.z);
        o.w = o.w > 0.f ? o.w : expm1f(o.w);
        oo[p] = o;
    }
    uint4 ob;
    *(__nv_bfloat162*)&ob.x = __floats2bfloat162_rn(oo[0].x, oo[0].y);
    *(__nv_bfloat162*)&ob.y = __floats2bfloat162_rn(oo[0].z, oo[0].w);
    *(__nv_bfloat162*)&ob.z = __floats2bfloat162_rn(oo[1].x, oo[1].y);
    *(__nv_bfloat162*)&ob.w = __floats2bfloat162_rn(oo[1].z, oo[1].w);
    ((uint4*)out)[node * 16 + q] = ob;
}

// ---------------- layer 2 fused aggregation (+pool) -------------------------
__global__ void __launch_bounds__(256, 6) agg_layer2(
        const int* __restrict__ srcs, const int* __restrict__ off,
        const float* __restrict__ aS, const float* __restrict__ aD,
        const __nv_bfloat16* __restrict__ H,
        const int* __restrict__ batch,
        float* __restrict__ gsum)
{
    __shared__ float sacc[16][DIM];
    __shared__ int   sbatch[16];
    int wid  = threadIdx.x >> 5;
    int lane = threadIdx.x & 31;
    int q    = lane & 15;
    int half = lane >> 4;
    int node = blockIdx.x * 16 + wid * 2 + half;   // always valid
    int nl   = wid * 2 + half;
    const uint4* H4 = (const uint4*)H;

    float aDn = aD[node];
    float den = ex2(leaky(aS[node * 16] + aDn));   // self loop
    float2 u0, u1, u2, u3;
    bf16x8_unpack(H4[node * 16 + q], u0, u1, u2, u3);
    float a0 = u0.x * den, a1 = u0.y * den, a2 = u1.x * den, a3 = u1.y * den;
    float a4 = u2.x * den, a5 = u2.y * den, a6 = u3.x * den, a7 = u3.y * den;

    int beg = off[node];
    int n   = off[node + 1] - beg;
    int noth = __shfl_xor_sync(0xffffffff, n, 16);
    int nqmin = min(n, noth) >> 2;
    int nqmax = max(n, noth) >> 2;
    int nq    = n >> 2;
    const int4* base = (const int4*)(srcs + beg);

    int iq = 0;
#pragma unroll 2
    for (; iq < nqmin; iq++) {
        int4 s4 = base[iq];
        AGG2_QUAD(s4);
    }
    for (; iq < nqmax; iq++) {
        int4 s4 = (iq < nq) ? base[iq] : *(const int4*)g_sentq;
        AGG2_QUAD(s4);
    }
    float inv = 1.f / den;
    a0 *= inv; a1 *= inv; a2 *= inv; a3 *= inv;
    a4 *= inv; a5 *= inv; a6 *= inv; a7 *= inv;
    int g = batch[node];

    if (q == 0) sbatch[nl] = g;
    float* sr = &sacc[nl][q * 8];
    sr[0] = a0; sr[1] = a1; sr[2] = a2; sr[3] = a3;
    sr[4] = a4; sr[5] = a5; sr[6] = a6; sr[7] = a7;
    __syncthreads();

    int g0 = sbatch[0];
    bool uniform = true;
#pragma unroll
    for (int w = 1; w < 16; w++) uniform &= (sbatch[w] == g0);

    if (uniform) {
        if (threadIdx.x < DIM) {
            float v = 0.f;
#pragma unroll
            for (int w = 0; w < 16; w++) v += sacc[w][threadIdx.x];
            atomicAdd(&gsum[g0 * DIM + threadIdx.x], v);
        }
    } else {
        float* dp = &gsum[g * DIM + q * 8];
        atomicAdd(dp + 0, a0); atomicAdd(dp + 1, a1);
        atomicAdd(dp + 2, a2); atomicAdd(dp + 3, a3);
        atomicAdd(dp + 4, a4); atomicAdd(dp + 5, a5);
        atomicAdd(dp + 6, a6); atomicAdd(dp + 7, a7);
    }
}

// ---------------- classifier MLP ---------------------------------------------
__global__ void classifier(const float* __restrict__ gsum, const float* __restrict__ gcnt,
                           const float* __restrict__ b2,
                           const float* __restrict__ Wc1, const float* __restrict__ bc1,
                           const float* __restrict__ Wc2, const float* __restrict__ bc2,
                           float* __restrict__ out)
{
    __shared__ float emb[DIM];
    __shared__ float z[64];
    int g = blockIdx.x, t = threadIdx.x;
    float cnt = fmaxf(gcnt[g], 1.f);
    emb[t] = gsum[g * DIM + t] / cnt + b2[t];
    __syncthreads();
    if (t < 64) {
        float a = bc1[t];
#pragma unroll 8
        for (int k = 0; k < DIM; k++) a = fmaf(emb[k], Wc1[k * 64 + t], a);
        z[t] = a > 0.f ? a : expm1f(a);
    }
    __syncthreads();
    if (t < NCLASS) {
        float a = bc2[t];
#pragma unroll
        for (int k = 0; k < 64; k++) a = fmaf(z[k], Wc2[k * NCLASS + t], a);
        out[g * NCLASS + t] = a;
    }
}

// ---------------- launch ------------------------------------------------------
extern "C" void kernel_launch(void* const* d_in, const int* in_sizes, int n_in,
                              void* d_out, int out_size)
{
    const float* x        = (const float*)d_in[0];
    const int*   esrc     = (const int*)  d_in[1];
    const int*   edst     = (const int*)  d_in[2];
    const int*   batch    = (const int*)  d_in[3];
    const float* W1       = (const float*)d_in[4];
    const float* b1       = (const float*)d_in[5];
    const float* att_src1 = (const float*)d_in[6];
    const float* att_dst1 = (const float*)d_in[7];
    const float* W2       = (const float*)d_in[8];
    const float* b2       = (const float*)d_in[9];
    const float* att_src2 = (const float*)d_in[10];
    const float* att_dst2 = (const float*)d_in[11];
    const float* bn_g     = (const float*)d_in[12];
    const float* bn_b     = (const float*)d_in[13];
    const float* bn_m     = (const float*)d_in[14];
    const float* bn_v     = (const float*)d_in[15];
    const float* Wc1      = (const float*)d_in[16];
    const float* bc1      = (const float*)d_in[17];
    const float* Wc2      = (const float*)d_in[18];
    const float* bc2      = (const float*)d_in[19];
    float* out = (float*)d_out;

    __nv_bfloat16 *p_h, *p_midb;
    float *p_w1p, *p_w2p, *p_as, *p_ad, *p_gsum, *p_gcnt;
    int *p_deg, *p_off, *p_cur, *p_srcs;
    cudaGetSymbolAddress((void**)&p_h,    g_h);
    cudaGetSymbolAddress((void**)&p_midb, g_midb);
    cudaGetSymbolAddress((void**)&p_w1p,  g_w1p);
    cudaGetSymbolAddress((void**)&p_w2p,  g_w2p);
    cudaGetSymbolAddress((void**)&p_as,   g_asrc);
    cudaGetSymbolAddress((void**)&p_ad,   g_adst);
    cudaGetSymbolAddress((void**)&p_deg,  g_deg);
    cudaGetSymbolAddress((void**)&p_off,  g_off);
    cudaGetSymbolAddress((void**)&p_cur,  g_cur);
    cudaGetSymbolAddress((void**)&p_srcs, g_srcs);
    cudaGetSymbolAddress((void**)&p_gsum, g_gsum);
    cudaGetSymbolAddress((void**)&p_gcnt, g_gcnt);

    static cudaStream_t s2 = 0;
    static cudaEvent_t evFork = 0, evJoin = 0;
    const int XSMEM = 128 * 132 * (int)sizeof(float);
    if (s2 == 0) {
        cudaStreamCreateWithFlags(&s2, cudaStreamNonBlocking);
        cudaEventCreateWithFlags(&evFork, cudaEventDisableTiming);
        cudaEventCreateWithFlags(&evJoin, cudaEventDisableTiming);
        cudaFuncSetAttribute(gemm_mma_kernel,
                             cudaFuncAttributeMaxDynamicSharedMemorySize, XSMEM);
    }

    const int TB = 256;
    int gemm_blocks = (N_NODES + 127) / 128;
    int agg_blocks  = N_NODES / 16;           // 3125

    cudaEventRecord(evFork, 0);
    cudaStreamWaitEvent(s2, evFork, 0);

    build_csr<<<NB_CSR, TB, 0, s2>>>(esrc, edst, batch, p_deg, p_off, p_cur,  // 0
                                     p_srcs, p_gsum, p_gcnt);
    cudaEventRecord(evJoin, s2);

    pack_w_tf32<<<(16 * 8 * 32 + TB - 1) / TB, TB>>>(W1, W2, p_w1p, p_w2p);   // 1
    gemm_mma_kernel<<<gemm_blocks, TB, XSMEM>>>(x, p_w1p, att_src1, att_dst1, // 2
                                                p_h, p_as, p_ad, HEADS, 0);
    cudaStreamWaitEvent(0, evJoin, 0);

    agg_layer1<<<agg_blocks, TB>>>(p_srcs, p_off, p_as, p_ad, p_h,            // 3 <- profiled
                                   b1, bn_g, bn_b, bn_m, bn_v, p_midb);
    gemm_mma_kernel<<<gemm_blocks, TB, XSMEM>>>((const float*)p_midb, p_w2p,  // 4
                                                att_src2, att_dst2, p_h, p_as, p_ad, 1, 1);
    agg_layer2<<<agg_blocks, TB>>>(p_srcs, p_off, p_as, p_ad, p_h, batch, p_gsum); // 5
    classifier<<<GRAPHS, DIM>>>(p_gsum, p_gcnt, b2, Wc1, bc1, Wc2, bc2, out);      // 6
}